// round 15
// baseline (speedup 1.0000x reference)
#include <cuda_runtime.h>
#include <cuda_bf16.h>
#include <math.h>
#include <stdint.h>

// Problem constants
#define BB 2
#define CC 64
#define HH 192
#define WW 192
#define HP 194   // padded
#define NTAP 9

typedef unsigned long long u64;
typedef unsigned int u32;

// ---------------- f32x2 packed helpers --------------------------------------
__device__ __forceinline__ u64 dup2(float x) {
    u64 r; asm("mov.b64 %0, {%1,%1};" : "=l"(r) : "f"(x)); return r;
}
__device__ __forceinline__ u64 pk2(float lo, float hi) {
    u64 r; asm("mov.b64 %0, {%1,%2};" : "=l"(r) : "f"(lo), "f"(hi)); return r;
}
__device__ __forceinline__ void fma2(u64 &d, u64 a, u64 b) {
    asm("fma.rn.f32x2 %0, %1, %2, %0;" : "+l"(d) : "l"(a), "l"(b));
}
__device__ __forceinline__ float2 unpk(u64 v) {
    float2 f; asm("mov.b64 {%0,%1}, %2;" : "=f"(f.x), "=f"(f.y) : "l"(v)); return f;
}

// ---------------- cp.async helpers -------------------------------------------
__device__ __forceinline__ void cpa4(u32 saddr, const void* g, int sz) {
    asm volatile("cp.async.ca.shared.global [%0], [%1], 4, %2;"
                 :: "r"(saddr), "l"(g), "r"(sz));
}
__device__ __forceinline__ void cpa_commit() {
    asm volatile("cp.async.commit_group;");
}
__device__ __forceinline__ void cpa_wait1() {
    asm volatile("cp.async.wait_group 1;");
}

// ---------------- scratch buffers (static device memory; no allocation) -----
__device__ float g_frpad[BB * CC * HP * HP];
__device__ float g_offset[BB * 18 * HH * WW];
__device__ float g_x[BB * CC * HH * WW];
__device__ float g_y[BB * CC * HH * WW];
__device__ float g_t1[BB * CC * 190 * 190];

// ---------------- pad kernel -------------------------------------------------
__global__ void pad_kernel(const float* __restrict__ src, float* __restrict__ dst) {
    int idx = blockIdx.x * blockDim.x + threadIdx.x;
    int total = BB * CC * HP * HP;
    if (idx >= total) return;
    int c2 = idx % HP;
    int r2 = (idx / HP) % HP;
    int bc = idx / (HP * HP);
    float v = 0.f;
    if (r2 >= 1 && r2 <= HH && c2 >= 1 && c2 <= WW)
        v = src[(size_t)bc * HH * WW + (r2 - 1) * WW + (c2 - 1)];
    dst[idx] = v;
}

// ---------------- generic 3x3 conv (kept for pconv, COUT=18) -----------------
template<int CIN, int COUT, int PADV, bool HAS_IN2>
__global__ void __launch_bounds__(256, 1)
conv3x3_kernel(const float* __restrict__ inA, const float* __restrict__ inB,
               const float* __restrict__ w, const float* __restrict__ bias,
               const float* __restrict__ res, float* __restrict__ out,
               int Hin, int Win, int Hout, int Wout)
{
    constexpr int CH = 8;
    constexpr int COUT_P = (COUT + 3) & ~3;
    __shared__ __align__(16) float sIn[CH][18][18];
    __shared__ __align__(16) float sW[CH * 9 * COUT_P];

    const int b   = blockIdx.z;
    const int ty0 = blockIdx.y * 16;
    const int tx0 = blockIdx.x * 16;
    const int tid = threadIdx.x;
    const int py = tid >> 4, px = tid & 15;
    const int oy = ty0 + py, ox = tx0 + px;

    float acc[COUT_P];
#pragma unroll
    for (int i = 0; i < COUT_P; i++) acc[i] = 0.f;

    const int cstride = HAS_IN2 ? 64 : CIN;

    for (int c0 = 0; c0 < CIN; c0 += CH) {
        for (int idx = tid; idx < CH * 18 * 18; idx += 256) {
            int c   = idx / (18 * 18);
            int rem = idx % (18 * 18);
            int r = rem / 18, cc = rem % 18;
            int iy = ty0 - PADV + r;
            int ix = tx0 - PADV + cc;
            float v = 0.f;
            if (iy >= 0 && iy < Hin && ix >= 0 && ix < Win) {
                int ci = c0 + c;
                const float* src = inA;
                int cl = ci;
                if (HAS_IN2 && ci >= 64) { src = inB; cl = ci - 64; }
                v = src[(((size_t)b * cstride + cl) * Hin + iy) * Win + ix];
            }
            sIn[c][r][cc] = v;
        }
        for (int idx = tid; idx < CH * 9 * COUT_P; idx += 256) {
            int co = idx % COUT_P;
            int ck = idx / COUT_P;
            int ci_l = ck / 9, k = ck % 9;
            float v = 0.f;
            if (co < COUT) v = w[((size_t)co * CIN + (c0 + ci_l)) * 9 + k];
            sW[idx] = v;
        }
        __syncthreads();

        for (int ci = 0; ci < CH; ci++) {
#pragma unroll
            for (int ky = 0; ky < 3; ky++) {
#pragma unroll
                for (int kx = 0; kx < 3; kx++) {
                    float xv = sIn[ci][py + ky][px + kx];
                    const float4* wp = reinterpret_cast<const float4*>(
                        &sW[(ci * 9 + ky * 3 + kx) * COUT_P]);
#pragma unroll
                    for (int j = 0; j < COUT_P / 4; j++) {
                        float4 w4 = wp[j];
                        acc[4 * j + 0] = fmaf(w4.x, xv, acc[4 * j + 0]);
                        acc[4 * j + 1] = fmaf(w4.y, xv, acc[4 * j + 1]);
                        acc[4 * j + 2] = fmaf(w4.z, xv, acc[4 * j + 2]);
                        acc[4 * j + 3] = fmaf(w4.w, xv, acc[4 * j + 3]);
                    }
                }
            }
        }
        __syncthreads();
    }

    if (oy < Hout && ox < Wout) {
        size_t obase = (size_t)b * COUT * Hout * Wout + (size_t)oy * Wout + ox;
        size_t cs = (size_t)Hout * Wout;
#pragma unroll
        for (int co = 0; co < COUT; co++) {
            float v = acc[co];
            if (bias) v += bias[co];
            if (res)  v += res[obase + co * cs];
            out[obase + co * cs] = v;
        }
    }
}

// ---------------- FFMA2 3x3 conv, 256-thread CTA, 2 CTAs/SM ------------------
// 256 threads = 2 cout-halves x 128 px-threads. Each thread: 1x2 px x 32 couts
// (16 f32x2 accs = 64 regs). Tile: 16 rows x 16 cols. Two CTAs co-reside per
// SM (128 regs x 256 thr = half RF; 59.9KB smem each) so barrier/pipeline
// stalls in one CTA are hidden by fma2 issue from the other.
// Dynamic SMEM float layout:
//   IN(buf)=buf*2880 : [CH][18][20] (18 cols used)
//   W(buf) =5760+buf*4608 : [CH][9][64]
#define CONV_SMEM_FLOATS (2*2880 + 2*4608)
template<int CIN, int PADV, bool HAS_IN2>
__global__ void __launch_bounds__(256, 2)
conv3x3_f2_kernel(const float* __restrict__ inA, const float* __restrict__ inB,
                  const float* __restrict__ w, const float* __restrict__ bias,
                  const float* __restrict__ res, const float* __restrict__ res2,
                  float* __restrict__ out,
                  int Hin, int Win, int Hout, int Wout)
{
    constexpr int CH = 8;
    constexpr int NC = CIN / CH;
    extern __shared__ __align__(16) float sm[];

    const int b   = blockIdx.z;
    const int ty0 = blockIdx.y * 16;
    const int tx0 = blockIdx.x * 16;
    const int tid = threadIdx.x;
    const int g   = tid >> 7;          // cout half
    const int t   = tid & 127;
    const int qy  = t >> 3;            // 0..15 output row
    const int qx  = t & 7;             // 0..7  output col pair

    const int cstride = HAS_IN2 ? 64 : CIN;
    const int HinWin = Hin * Win;
    const u32 smem_base = (u32)__cvta_generic_to_shared(sm);

    // ---- hoisted staging geometry (chunk-invariant, division-free loop) ----
    // input positions: p in [0, 18*18=324); thread owns p0=tid, p1=tid+256
    const int p0 = tid;
    const int r0 = p0 / 18, q0 = p0 % 18;
    const int iy0 = ty0 - PADV + r0, ix0 = tx0 - PADV + q0;
    const bool ok0 = (iy0 >= 0 && iy0 < Hin && ix0 >= 0 && ix0 < Win);
    const int go0 = iy0 * Win + ix0;
    const u32 so0 = (u32)((r0 * 20 + q0) * 4);
    const int p1 = tid + 256;
    const bool has1 = (p1 < 324);
    const int r1 = p1 / 18, q1 = p1 % 18;
    const int iy1 = ty0 - PADV + r1, ix1 = tx0 - PADV + q1;
    const bool ok1 = has1 && (iy1 >= 0 && iy1 < Hin && ix1 >= 0 && ix1 < Win);
    const int go1 = iy1 * Win + ix1;
    const u32 so1 = (u32)((r1 * 20 + q1) * 4);
    // weights: thread owns co=tid&63, pair index wp0=tid>>6 (0..3), 18 steps of 4
    const int wco = tid & 63;
    const int wp0 = tid >> 6;
    const size_t wbase0 = (size_t)wco * CIN * 9 + wp0;

    auto stage = [&](int buf, int cc0_) {
        const float* srcb;
        if (HAS_IN2 && cc0_ >= 64)
            srcb = inB + ((size_t)b * 64 + (cc0_ - 64)) * HinWin;
        else
            srcb = inA + ((size_t)b * cstride + cc0_) * HinWin;
        const u32 sbase = smem_base + (u32)(buf * 2880 * 4);
        {
            const float* gp = ok0 ? (srcb + go0) : srcb;
            const int step = ok0 ? HinWin : 0;
            const int sz = ok0 ? 4 : 0;
            u32 sa = sbase + so0;
#pragma unroll
            for (int c = 0; c < CH; c++) {
                cpa4(sa, gp, sz);
                gp += step; sa += 360 * 4;   // 18*20 floats per channel
            }
        }
        if (has1) {
            const float* gp = ok1 ? (srcb + go1) : srcb;
            const int step = ok1 ? HinWin : 0;
            const int sz = ok1 ? 4 : 0;
            u32 sa = sbase + so1;
#pragma unroll
            for (int c = 0; c < CH; c++) {
                cpa4(sa, gp, sz);
                gp += step; sa += 360 * 4;
            }
        }
        {
            // weight pairs wp = wp0 + 4*m, m = 0..17 (8 ci x 9 taps = 72 pairs)
            const float* gp = w + wbase0 + (size_t)cc0_ * 9;
            u32 sa = smem_base + (u32)((5760 + buf * 4608 + wp0 * 64 + wco) * 4);
#pragma unroll
            for (int m = 0; m < 18; m++) {
                cpa4(sa, gp, 4);
                gp += 4; sa += 1024;   // 4 pairs * 64 floats * 4B
            }
        }
    };

    u64 acc[2][16];
#pragma unroll
    for (int p = 0; p < 2; p++)
#pragma unroll
        for (int j = 0; j < 16; j++) acc[p][j] = 0ull;

    stage(0, 0);
    cpa_commit();

    for (int c = 0; c < NC; c++) {
        int buf = c & 1;
        if (c + 1 < NC) stage(buf ^ 1, (c + 1) * CH);
        cpa_commit();
        cpa_wait1();
        __syncthreads();

        const float* sIn = sm + buf * 2880;          // [CH][18][20]
        const float* sW  = sm + 5760 + buf * 4608;   // [CH][9][64]

#pragma unroll 1
        for (int ci = 0; ci < CH; ci++) {
            u64 d[3][4];
#pragma unroll
            for (int r = 0; r < 3; r++) {
                const float2* ip = reinterpret_cast<const float2*>(
                    &sIn[(ci * 18 + qy + r) * 20 + 2 * qx]);
                float2 a = ip[0], bb = ip[1];
                d[r][0] = dup2(a.x); d[r][1] = dup2(a.y);
                d[r][2] = dup2(bb.x); d[r][3] = dup2(bb.y);
            }
#pragma unroll
            for (int ky = 0; ky < 3; ky++) {
#pragma unroll
                for (int kx = 0; kx < 3; kx++) {
                    u64 xv0 = d[ky][kx];
                    u64 xv1 = d[ky][kx + 1];
                    const ulonglong2* wp = reinterpret_cast<const ulonglong2*>(
                        &sW[(ci * 9 + ky * 3 + kx) * 64 + g * 32]);
#pragma unroll
                    for (int j = 0; j < 8; j++) {
                        ulonglong2 q = wp[j];
                        fma2(acc[0][2 * j],     xv0, q.x);
                        fma2(acc[0][2 * j + 1], xv0, q.y);
                        fma2(acc[1][2 * j],     xv1, q.x);
                        fma2(acc[1][2 * j + 1], xv1, q.y);
                    }
                }
            }
        }
        __syncthreads();
    }

    // store
    size_t cs = (size_t)Hout * Wout;
    int oy = ty0 + qy;
#pragma unroll
    for (int pc = 0; pc < 2; pc++) {
        int ox = tx0 + 2 * qx + pc;
        if (oy < Hout && ox < Wout) {
            size_t base = (size_t)b * 64 * cs + (size_t)oy * Wout + ox;
            u64* ac = acc[pc];
#pragma unroll
            for (int j = 0; j < 16; j++) {
                float2 v = unpk(ac[j]);
                int co = g * 32 + 2 * j;
                float o0 = v.x, o1 = v.y;
                if (bias) { o0 += bias[co]; o1 += bias[co + 1]; }
                if (res)  { o0 += res[base + (size_t)co * cs];
                            o1 += res[base + (size_t)(co + 1) * cs]; }
                if (res2) { o0 += res2[base + (size_t)co * cs];
                            o1 += res2[base + (size_t)(co + 1) * cs]; }
                out[base + (size_t)co * cs]       = o0;
                out[base + (size_t)(co + 1) * cs] = o1;
            }
        }
    }
}

// ---------------- deformable conv, FFMA2, all-tap weights in SMEM ------------
#define DEF_SMEM_FLOATS (9 * 64 * 64)
__global__ void __launch_bounds__(512, 1)
deform_f2_kernel(const float* __restrict__ xpad,    // (B,64,194,194)
                 const float* __restrict__ offset,  // (B,18,192,192)
                 const float* __restrict__ wdc,     // (64,64,3,3)
                 float* __restrict__ out)           // (B,64,192,192)
{
    extern __shared__ __align__(16) float sW[];     // [tap][ci][co]

    const int b   = blockIdx.z;
    const int ty0 = blockIdx.y * 16;
    const int tx0 = blockIdx.x * 32;
    const int tid = threadIdx.x;
    const int py  = tid >> 5, px = tid & 31;
    const int i   = ty0 + py;
    const int j   = tx0 + px;

    for (int idx = tid; idx < 9 * 64 * 64; idx += 512) {
        int tap = idx >> 12;
        int r   = idx & 4095;
        int ci  = r >> 6, co = r & 63;
        sW[idx] = wdc[((size_t)co * 64 + ci) * 9 + tap];
    }
    __syncthreads();

    u64 acc[32];
#pragma unroll
    for (int c = 0; c < 32; c++) acc[c] = 0ull;

#pragma unroll 1
    for (int n = 0; n < NTAP; n++) {
        int dr = n / 3 - 1, dc = n % 3 - 1;
        float offr = offset[(((size_t)b * 18 + n) * HH + i) * WW + j];
        float offc = offset[(((size_t)b * 18 + 9 + n) * HH + i) * WW + j];
        float p_r = (float)(i + 1 + dr) + offr;
        float p_c = (float)(j + 1 + dc) + offc;
        float pr = fminf(fmaxf(p_r, 0.f), 193.f);
        float pc = fminf(fmaxf(p_c, 0.f), 193.f);
        float fr = floorf(p_r), fc = floorf(p_c);
        float qr0 = fminf(fmaxf(fr,       0.f), 193.f);
        float qc0 = fminf(fmaxf(fc,       0.f), 193.f);
        float qr1 = fminf(fmaxf(fr + 1.f, 0.f), 193.f);
        float qc1 = fminf(fmaxf(fc + 1.f, 0.f), 193.f);
        float glt = (1.f + (qr0 - pr)) * (1.f + (qc0 - pc));
        float grb = (1.f - (qr1 - pr)) * (1.f - (qc1 - pc));
        float glb = (1.f + (qr0 - pr)) * (1.f - (qc1 - pc));
        float grt = (1.f - (qr1 - pr)) * (1.f + (qc0 - pc));
        int i00 = (int)qr0 * HP + (int)qc0;
        int i11 = (int)qr1 * HP + (int)qc1;
        int i01 = (int)qr0 * HP + (int)qc1;
        int i10 = (int)qr1 * HP + (int)qc0;

        const float* xb = xpad + (size_t)b * 64 * HP * HP;
        const float* wn = &sW[n * 4096];
#pragma unroll 1
        for (int ci = 0; ci < 64; ci++) {
            const float* xc = xb + (size_t)ci * HP * HP;
            float xo = glt * xc[i00] + grb * xc[i11]
                     + glb * xc[i01] + grt * xc[i10];
            u64 x2 = dup2(xo);
            const ulonglong2* wp = reinterpret_cast<const ulonglong2*>(&wn[ci * 64]);
#pragma unroll
            for (int jj = 0; jj < 16; jj++) {
                ulonglong2 q = wp[jj];
                fma2(acc[2 * jj],     x2, q.x);
                fma2(acc[2 * jj + 1], x2, q.y);
            }
        }
    }

    size_t obase = (size_t)b * 64 * HH * WW + (size_t)i * WW + j;
#pragma unroll
    for (int jj = 0; jj < 32; jj++) {
        float2 v = unpk(acc[jj]);
        out[obase + (size_t)(2 * jj)     * HH * WW] = v.x;
        out[obase + (size_t)(2 * jj + 1) * HH * WW] = v.y;
    }
}

// ---------------- GDN + celu (in place), FFMA2 -------------------------------
__global__ void __launch_bounds__(256, 1)
gdn_celu_kernel(float* __restrict__ x, const float* __restrict__ beta,
                const float* __restrict__ gamma, int HWp)
{
    __shared__ __align__(16) float sG[64 * 64];  // sG[ci*64+co] = gamma[co][ci]
    __shared__ float sB[64];
    const int tid = threadIdx.x;
    for (int idx = tid; idx < 4096; idx += 256) {
        int co = idx & 63, ci = idx >> 6;
        sG[idx] = gamma[co * 64 + ci];
    }
    if (tid < 64) sB[tid] = beta[tid];
    __syncthreads();

    int p = blockIdx.x * 256 + tid;
    if (p >= BB * HWp) return;
    int b = p / HWp, hw = p % HWp;
    float* base = x + (size_t)b * 64 * HWp + hw;

    u64 nrm[32];
#pragma unroll
    for (int jj = 0; jj < 32; jj++) nrm[jj] = pk2(sB[2 * jj], sB[2 * jj + 1]);

    for (int ci = 0; ci < 64; ci++) {
        float v = base[(size_t)ci * HWp];
        u64 sq = dup2(v * v);
        const ulonglong2* gp = reinterpret_cast<const ulonglong2*>(&sG[ci * 64]);
#pragma unroll
        for (int jj = 0; jj < 16; jj++) {
            ulonglong2 q = gp[jj];
            fma2(nrm[2 * jj],     sq, q.x);
            fma2(nrm[2 * jj + 1], sq, q.y);
        }
    }
#pragma unroll
    for (int jj = 0; jj < 32; jj++) {
        float2 nv = unpk(nrm[jj]);
        float v0 = base[(size_t)(2 * jj) * HWp];
        float v1 = base[(size_t)(2 * jj + 1) * HWp];
        float t0 = v0 * rsqrtf(nv.x);
        float t1 = v1 * rsqrtf(nv.y);
        base[(size_t)(2 * jj) * HWp]     = (t0 > 0.f) ? t0 : expm1f(t0);
        base[(size_t)(2 * jj + 1) * HWp] = (t1 > 0.f) ? t1 : expm1f(t1);
    }
}

// ---------------- launcher ---------------------------------------------------
extern "C" void kernel_launch(void* const* d_in, const int* in_sizes, int n_in,
                              void* d_out, int out_size)
{
    const float* f_r     = (const float*)d_in[0];
    const float* m_t     = (const float*)d_in[1];
    const float* w_pconv = (const float*)d_in[2];
    const float* b_pconv = (const float*)d_in[3];
    const float* w_dc    = (const float*)d_in[4];
    const float* w_cat   = (const float*)d_in[5];
    const float* b_cat   = (const float*)d_in[6];
    const float* rb_w1   = (const float*)d_in[7];
    const float* rb_w2   = (const float*)d_in[8];
    const float* rb_beta = (const float*)d_in[9];
    const float* rb_gamma= (const float*)d_in[10];
    float* out = (float*)d_out;

    float *frpad, *offs, *xbuf, *ybuf, *t1;
    cudaGetSymbolAddress((void**)&frpad, g_frpad);
    cudaGetSymbolAddress((void**)&offs,  g_offset);
    cudaGetSymbolAddress((void**)&xbuf,  g_x);
    cudaGetSymbolAddress((void**)&ybuf,  g_y);
    cudaGetSymbolAddress((void**)&t1,    g_t1);

    const int conv_smem = CONV_SMEM_FLOATS * 4;   // 59904 B
    const int def_smem  = DEF_SMEM_FLOATS  * 4;   // 147456 B
    cudaFuncSetAttribute(conv3x3_f2_kernel<128, 1, true>,
                         cudaFuncAttributeMaxDynamicSharedMemorySize, conv_smem);
    cudaFuncSetAttribute(conv3x3_f2_kernel<64, 0, false>,
                         cudaFuncAttributeMaxDynamicSharedMemorySize, conv_smem);
    cudaFuncSetAttribute(conv3x3_f2_kernel<64, 2, false>,
                         cudaFuncAttributeMaxDynamicSharedMemorySize, conv_smem);
    cudaFuncSetAttribute(deform_f2_kernel,
                         cudaFuncAttributeMaxDynamicSharedMemorySize, def_smem);

    // 1. pad f_r
    {
        int total = BB * CC * HP * HP;
        pad_kernel<<<(total + 255) / 256, 256>>>(f_r, frpad);
    }
    // 2. offset = pconv(m_t), pad 1, 64->18
    {
        dim3 grid(12, 12, BB);
        conv3x3_kernel<64, 18, 1, false><<<grid, 256>>>(
            m_t, nullptr, w_pconv, b_pconv, nullptr, offs, HH, WW, HH, WW);
    }
    // 3. x = deform_conv(f_r, offset, w_dc)
    {
        dim3 grid(6, 12, BB);
        deform_f2_kernel<<<grid, 512, def_smem>>>(frpad, offs, w_dc, xbuf);
    }
    // 4. y = conv(cat[x, f_r]), pad 1, 128->64  (16x16 tiles, 256 thr, 2 CTA/SM)
    {
        dim3 grid(12, 12, BB);
        conv3x3_f2_kernel<128, 1, true><<<grid, 256, conv_smem>>>(
            xbuf, f_r, w_cat, b_cat, nullptr, nullptr, ybuf, HH, WW, HH, WW);
    }
    // 5. resblocks
    for (int l = 0; l < 3; l++) {
        const float* w1 = rb_w1 + (size_t)l * 64 * 64 * 9;
        const float* w2 = rb_w2 + (size_t)l * 64 * 64 * 9;
        const float* bt = rb_beta + (size_t)l * 64;
        const float* gm = rb_gamma + (size_t)l * 64 * 64;
        // conv1: pad 0, 192 -> 190
        {
            dim3 grid(12, 12, BB);   // ceil(190/16)=12
            conv3x3_f2_kernel<64, 0, false><<<grid, 256, conv_smem>>>(
                ybuf, nullptr, w1, nullptr, nullptr, nullptr, t1, HH, WW, 190, 190);
        }
        // gdn + celu in place on t1
        {
            int HWp = 190 * 190;
            int total = BB * HWp;
            gdn_celu_kernel<<<(total + 255) / 256, 256>>>(t1, bt, gm, HWp);
        }
        // conv2: pad 2, 190 -> 192, + residual y.
        // Last layer: also add x (res2) and write straight to harness output.
        {
            dim3 grid(12, 12, BB);
            if (l < 2) {
                conv3x3_f2_kernel<64, 2, false><<<grid, 256, conv_smem>>>(
                    t1, nullptr, w2, nullptr, ybuf, nullptr, ybuf, 190, 190, HH, WW);
            } else {
                conv3x3_f2_kernel<64, 2, false><<<grid, 256, conv_smem>>>(
                    t1, nullptr, w2, nullptr, ybuf, xbuf, out, 190, 190, HH, WW);
            }
        }
    }
}

// round 16
// speedup vs baseline: 1.1376x; 1.1376x over previous
#include <cuda_runtime.h>
#include <cuda_bf16.h>
#include <math.h>
#include <stdint.h>

// Problem constants
#define BB 2
#define CC 64
#define HH 192
#define WW 192
#define HP 194   // padded
#define NTAP 9

typedef unsigned long long u64;
typedef unsigned int u32;

// ---------------- f32x2 packed helpers --------------------------------------
__device__ __forceinline__ u64 dup2(float x) {
    u64 r; asm("mov.b64 %0, {%1,%1};" : "=l"(r) : "f"(x)); return r;
}
__device__ __forceinline__ u64 pk2(float lo, float hi) {
    u64 r; asm("mov.b64 %0, {%1,%2};" : "=l"(r) : "f"(lo), "f"(hi)); return r;
}
__device__ __forceinline__ void fma2(u64 &d, u64 a, u64 b) {
    asm("fma.rn.f32x2 %0, %1, %2, %0;" : "+l"(d) : "l"(a), "l"(b));
}
__device__ __forceinline__ float2 unpk(u64 v) {
    float2 f; asm("mov.b64 {%0,%1}, %2;" : "=f"(f.x), "=f"(f.y) : "l"(v)); return f;
}

// ---------------- cp.async helpers -------------------------------------------
__device__ __forceinline__ void cpa4(u32 saddr, const void* g, int sz) {
    asm volatile("cp.async.ca.shared.global [%0], [%1], 4, %2;"
                 :: "r"(saddr), "l"(g), "r"(sz));
}
__device__ __forceinline__ void cpa_commit() {
    asm volatile("cp.async.commit_group;");
}
__device__ __forceinline__ void cpa_wait1() {
    asm volatile("cp.async.wait_group 1;");
}

// ---------------- scratch buffers (static device memory; no allocation) -----
__device__ float g_frpad[BB * CC * HP * HP];
__device__ float g_offset[BB * 18 * HH * WW];
__device__ float g_x[BB * CC * HH * WW];
__device__ float g_y[BB * CC * HH * WW];
__device__ float g_t1[BB * CC * 190 * 190];

// ---------------- pad kernel -------------------------------------------------
__global__ void pad_kernel(const float* __restrict__ src, float* __restrict__ dst) {
    int idx = blockIdx.x * blockDim.x + threadIdx.x;
    int total = BB * CC * HP * HP;
    if (idx >= total) return;
    int c2 = idx % HP;
    int r2 = (idx / HP) % HP;
    int bc = idx / (HP * HP);
    float v = 0.f;
    if (r2 >= 1 && r2 <= HH && c2 >= 1 && c2 <= WW)
        v = src[(size_t)bc * HH * WW + (r2 - 1) * WW + (c2 - 1)];
    dst[idx] = v;
}

// ---------------- generic 3x3 conv (kept for pconv, COUT=18) -----------------
template<int CIN, int COUT, int PADV, bool HAS_IN2>
__global__ void __launch_bounds__(256, 1)
conv3x3_kernel(const float* __restrict__ inA, const float* __restrict__ inB,
               const float* __restrict__ w, const float* __restrict__ bias,
               const float* __restrict__ res, float* __restrict__ out,
               int Hin, int Win, int Hout, int Wout)
{
    constexpr int CH = 8;
    constexpr int COUT_P = (COUT + 3) & ~3;
    __shared__ __align__(16) float sIn[CH][18][18];
    __shared__ __align__(16) float sW[CH * 9 * COUT_P];

    const int b   = blockIdx.z;
    const int ty0 = blockIdx.y * 16;
    const int tx0 = blockIdx.x * 16;
    const int tid = threadIdx.x;
    const int py = tid >> 4, px = tid & 15;
    const int oy = ty0 + py, ox = tx0 + px;

    float acc[COUT_P];
#pragma unroll
    for (int i = 0; i < COUT_P; i++) acc[i] = 0.f;

    const int cstride = HAS_IN2 ? 64 : CIN;

    for (int c0 = 0; c0 < CIN; c0 += CH) {
        for (int idx = tid; idx < CH * 18 * 18; idx += 256) {
            int c   = idx / (18 * 18);
            int rem = idx % (18 * 18);
            int r = rem / 18, cc = rem % 18;
            int iy = ty0 - PADV + r;
            int ix = tx0 - PADV + cc;
            float v = 0.f;
            if (iy >= 0 && iy < Hin && ix >= 0 && ix < Win) {
                int ci = c0 + c;
                const float* src = inA;
                int cl = ci;
                if (HAS_IN2 && ci >= 64) { src = inB; cl = ci - 64; }
                v = src[(((size_t)b * cstride + cl) * Hin + iy) * Win + ix];
            }
            sIn[c][r][cc] = v;
        }
        for (int idx = tid; idx < CH * 9 * COUT_P; idx += 256) {
            int co = idx % COUT_P;
            int ck = idx / COUT_P;
            int ci_l = ck / 9, k = ck % 9;
            float v = 0.f;
            if (co < COUT) v = w[((size_t)co * CIN + (c0 + ci_l)) * 9 + k];
            sW[idx] = v;
        }
        __syncthreads();

        for (int ci = 0; ci < CH; ci++) {
#pragma unroll
            for (int ky = 0; ky < 3; ky++) {
#pragma unroll
                for (int kx = 0; kx < 3; kx++) {
                    float xv = sIn[ci][py + ky][px + kx];
                    const float4* wp = reinterpret_cast<const float4*>(
                        &sW[(ci * 9 + ky * 3 + kx) * COUT_P]);
#pragma unroll
                    for (int j = 0; j < COUT_P / 4; j++) {
                        float4 w4 = wp[j];
                        acc[4 * j + 0] = fmaf(w4.x, xv, acc[4 * j + 0]);
                        acc[4 * j + 1] = fmaf(w4.y, xv, acc[4 * j + 1]);
                        acc[4 * j + 2] = fmaf(w4.z, xv, acc[4 * j + 2]);
                        acc[4 * j + 3] = fmaf(w4.w, xv, acc[4 * j + 3]);
                    }
                }
            }
        }
        __syncthreads();
    }

    if (oy < Hout && ox < Wout) {
        size_t obase = (size_t)b * COUT * Hout * Wout + (size_t)oy * Wout + ox;
        size_t cs = (size_t)Hout * Wout;
#pragma unroll
        for (int co = 0; co < COUT; co++) {
            float v = acc[co];
            if (bias) v += bias[co];
            if (res)  v += res[obase + co * cs];
            out[obase + co * cs] = v;
        }
    }
}

// Shared SMEM layout for both f2 conv variants (512 threads, 16x32 tile):
//   IN(buf)=buf*5184 : [CH][18][36] (34 cols used)
//   W(buf) =10368+buf*4608 : [CH][9][64]
#define CONV_SMEM_FLOATS (2*5184 + 2*4608)

// ---------------- staging geometry shared by both variants -------------------
// (division-free cp.async staging; hoisted per-thread positions)
#define CONV_STAGE_DECLS                                                      \
    const int HinWin = Hin * Win;                                             \
    const u32 smem_base = (u32)__cvta_generic_to_shared(sm);                  \
    const int p0_ = tid;                                                      \
    const int r0_ = p0_ / 34, q0_ = p0_ % 34;                                 \
    const int iy0_ = ty0 - PADV + r0_, ix0_ = tx0 - PADV + q0_;               \
    const bool ok0_ = (iy0_ >= 0 && iy0_ < Hin && ix0_ >= 0 && ix0_ < Win);   \
    const int go0_ = iy0_ * Win + ix0_;                                       \
    const u32 so0_ = (u32)((r0_ * 36 + q0_) * 4);                             \
    const int p1_ = tid + 512;                                                \
    const bool has1_ = (p1_ < 612);                                           \
    const int r1_ = p1_ / 34, q1_ = p1_ % 34;                                 \
    const int iy1_ = ty0 - PADV + r1_, ix1_ = tx0 - PADV + q1_;               \
    const bool ok1_ = has1_ && (iy1_ >= 0 && iy1_ < Hin && ix1_ >= 0 && ix1_ < Win); \
    const int go1_ = iy1_ * Win + ix1_;                                       \
    const u32 so1_ = (u32)((r1_ * 36 + q1_) * 4);                             \
    const int wco_ = tid & 63;                                                \
    const int wp0_ = tid >> 6;                                                \
    const size_t wbase0_ = (size_t)wco_ * CIN * 9 + wp0_;                     \
    auto stage = [&](int buf, int cc0_) {                                     \
        const float* srcb;                                                    \
        if (HAS_IN2 && cc0_ >= 64)                                            \
            srcb = inB + ((size_t)b * 64 + (cc0_ - 64)) * HinWin;             \
        else                                                                  \
            srcb = inA + ((size_t)b * cstride + cc0_) * HinWin;               \
        const u32 sbase = smem_base + (u32)(buf * 5184 * 4);                  \
        {                                                                     \
            const float* gp = ok0_ ? (srcb + go0_) : srcb;                    \
            const int step = ok0_ ? HinWin : 0;                               \
            const int sz = ok0_ ? 4 : 0;                                      \
            u32 sa = sbase + so0_;                                            \
            _Pragma("unroll")                                                 \
            for (int c = 0; c < CH; c++) { cpa4(sa, gp, sz); gp += step; sa += 648 * 4; } \
        }                                                                     \
        if (has1_) {                                                          \
            const float* gp = ok1_ ? (srcb + go1_) : srcb;                    \
            const int step = ok1_ ? HinWin : 0;                               \
            const int sz = ok1_ ? 4 : 0;                                      \
            u32 sa = sbase + so1_;                                            \
            _Pragma("unroll")                                                 \
            for (int c = 0; c < CH; c++) { cpa4(sa, gp, sz); gp += step; sa += 648 * 4; } \
        }                                                                     \
        {                                                                     \
            const float* gp = w + wbase0_ + (size_t)cc0_ * 9;                 \
            u32 sa = smem_base + (u32)((10368 + buf * 4608 + wp0_ * 64 + wco_) * 4); \
            _Pragma("unroll")                                                 \
            for (int m = 0; m < 9; m++) { cpa4(sa, gp, 4); gp += 8; sa += 2048; } \
        }                                                                     \
    };

// ---------------- PAIR variant (R8): 1x2 px x 32 couts — best for CIN=64 -----
template<int CIN, int PADV, bool HAS_IN2>
__global__ void __launch_bounds__(512, 1)
conv3x3_f2_pair(const float* __restrict__ inA, const float* __restrict__ inB,
                const float* __restrict__ w, const float* __restrict__ bias,
                const float* __restrict__ res, const float* __restrict__ res2,
                float* __restrict__ out,
                int Hin, int Win, int Hout, int Wout)
{
    constexpr int CH = 8;
    constexpr int NC = CIN / CH;
    extern __shared__ __align__(16) float sm[];

    const int b   = blockIdx.z;
    const int ty0 = blockIdx.y * 16;
    const int tx0 = blockIdx.x * 32;
    const int tid = threadIdx.x;
    const int g   = tid >> 8;          // cout half
    const int t   = tid & 255;
    const int qy  = t >> 4;            // 0..15 output row
    const int qx  = t & 15;            // 0..15 output col pair

    const int cstride = HAS_IN2 ? 64 : CIN;
    CONV_STAGE_DECLS

    u64 acc[2][16];
#pragma unroll
    for (int p = 0; p < 2; p++)
#pragma unroll
        for (int j = 0; j < 16; j++) acc[p][j] = 0ull;

    stage(0, 0);
    cpa_commit();

    for (int c = 0; c < NC; c++) {
        int buf = c & 1;
        if (c + 1 < NC) stage(buf ^ 1, (c + 1) * CH);
        cpa_commit();
        cpa_wait1();
        __syncthreads();

        const float* sIn = sm + buf * 5184;          // [CH][18][36]
        const float* sW  = sm + 10368 + buf * 4608;  // [CH][9][64]

#pragma unroll 1
        for (int ci = 0; ci < CH; ci++) {
            u64 d[3][4];
#pragma unroll
            for (int r = 0; r < 3; r++) {
                const float2* ip = reinterpret_cast<const float2*>(
                    &sIn[(ci * 18 + qy + r) * 36 + 2 * qx]);
                float2 a = ip[0], bb = ip[1];
                d[r][0] = dup2(a.x); d[r][1] = dup2(a.y);
                d[r][2] = dup2(bb.x); d[r][3] = dup2(bb.y);
            }
#pragma unroll
            for (int ky = 0; ky < 3; ky++) {
#pragma unroll
                for (int kx = 0; kx < 3; kx++) {
                    u64 xv0 = d[ky][kx];
                    u64 xv1 = d[ky][kx + 1];
                    const ulonglong2* wp = reinterpret_cast<const ulonglong2*>(
                        &sW[(ci * 9 + ky * 3 + kx) * 64 + g * 32]);
#pragma unroll
                    for (int j = 0; j < 8; j++) {
                        ulonglong2 q = wp[j];
                        fma2(acc[0][2 * j],     xv0, q.x);
                        fma2(acc[0][2 * j + 1], xv0, q.y);
                        fma2(acc[1][2 * j],     xv1, q.x);
                        fma2(acc[1][2 * j + 1], xv1, q.y);
                    }
                }
            }
        }
        __syncthreads();
    }

    size_t cs = (size_t)Hout * Wout;
    int oy = ty0 + qy;
#pragma unroll
    for (int pc = 0; pc < 2; pc++) {
        int ox = tx0 + 2 * qx + pc;
        if (oy < Hout && ox < Wout) {
            size_t base = (size_t)b * 64 * cs + (size_t)oy * Wout + ox;
            u64* ac = acc[pc];
#pragma unroll
            for (int j = 0; j < 16; j++) {
                float2 v = unpk(ac[j]);
                int co = g * 32 + 2 * j;
                float o0 = v.x, o1 = v.y;
                if (bias) { o0 += bias[co]; o1 += bias[co + 1]; }
                if (res)  { o0 += res[base + (size_t)co * cs];
                            o1 += res[base + (size_t)(co + 1) * cs]; }
                if (res2) { o0 += res2[base + (size_t)co * cs];
                            o1 += res2[base + (size_t)(co + 1) * cs]; }
                out[base + (size_t)co * cs]       = o0;
                out[base + (size_t)(co + 1) * cs] = o1;
            }
        }
    }
}

// ---------------- QUAD variant (R11): 2x2 px x 16 couts — best for CIN=128 ---
template<int CIN, int PADV, bool HAS_IN2>
__global__ void __launch_bounds__(512, 1)
conv3x3_f2_quad(const float* __restrict__ inA, const float* __restrict__ inB,
                const float* __restrict__ w, const float* __restrict__ bias,
                const float* __restrict__ res, const float* __restrict__ res2,
                float* __restrict__ out,
                int Hin, int Win, int Hout, int Wout)
{
    constexpr int CH = 8;
    constexpr int NC = CIN / CH;
    extern __shared__ __align__(16) float sm[];

    const int b   = blockIdx.z;
    const int ty0 = blockIdx.y * 16;
    const int tx0 = blockIdx.x * 32;
    const int tid = threadIdx.x;
    const int g   = tid >> 7;          // cout group 0..3 (16 couts)
    const int t   = tid & 127;
    const int ty  = t >> 4;            // 0..7  output row pair
    const int qx  = t & 15;            // 0..15 output col pair

    const int cstride = HAS_IN2 ? 64 : CIN;
    CONV_STAGE_DECLS

    u64 acc[4][8];
#pragma unroll
    for (int p = 0; p < 4; p++)
#pragma unroll
        for (int j = 0; j < 8; j++) acc[p][j] = 0ull;

    stage(0, 0);
    cpa_commit();

    for (int c = 0; c < NC; c++) {
        int buf = c & 1;
        if (c + 1 < NC) stage(buf ^ 1, (c + 1) * CH);
        cpa_commit();
        cpa_wait1();
        __syncthreads();

        const float* sIn = sm + buf * 5184;          // [CH][18][36]
        const float* sW  = sm + 10368 + buf * 4608;  // [CH][9][64]

#pragma unroll 1
        for (int ci = 0; ci < CH; ci++) {
#pragma unroll
            for (int ky = 0; ky < 3; ky++) {
                u64 d[2][4];
#pragma unroll
                for (int r = 0; r < 2; r++) {
                    const float2* ip = reinterpret_cast<const float2*>(
                        &sIn[(ci * 18 + 2 * ty + ky + r) * 36 + 2 * qx]);
                    float2 a = ip[0], bb = ip[1];
                    d[r][0] = dup2(a.x); d[r][1] = dup2(a.y);
                    d[r][2] = dup2(bb.x); d[r][3] = dup2(bb.y);
                }
#pragma unroll
                for (int kx = 0; kx < 3; kx++) {
                    const ulonglong2* wp = reinterpret_cast<const ulonglong2*>(
                        &sW[(ci * 9 + ky * 3 + kx) * 64 + g * 16]);
                    ulonglong2 w01 = wp[0];
                    ulonglong2 w23 = wp[1];
#pragma unroll
                    for (int pr = 0; pr < 2; pr++) {
#pragma unroll
                        for (int pc = 0; pc < 2; pc++) {
                            u64 xv = d[pr][pc + kx];
                            u64* a = acc[pr * 2 + pc];
                            fma2(a[0], xv, w01.x);
                            fma2(a[1], xv, w01.y);
                            fma2(a[2], xv, w23.x);
                            fma2(a[3], xv, w23.y);
                        }
                    }
                    ulonglong2 w45 = wp[2];
                    ulonglong2 w67 = wp[3];
#pragma unroll
                    for (int pr = 0; pr < 2; pr++) {
#pragma unroll
                        for (int pc = 0; pc < 2; pc++) {
                            u64 xv = d[pr][pc + kx];
                            u64* a = acc[pr * 2 + pc];
                            fma2(a[4], xv, w45.x);
                            fma2(a[5], xv, w45.y);
                            fma2(a[6], xv, w67.x);
                            fma2(a[7], xv, w67.y);
                        }
                    }
                }
            }
        }
        __syncthreads();
    }

    size_t cs = (size_t)Hout * Wout;
#pragma unroll
    for (int pr = 0; pr < 2; pr++) {
        int oy = ty0 + 2 * ty + pr;
        if (oy >= Hout) continue;
#pragma unroll
        for (int pc = 0; pc < 2; pc++) {
            int ox = tx0 + 2 * qx + pc;
            if (ox >= Wout) continue;
            size_t base = (size_t)b * 64 * cs + (size_t)oy * Wout + ox;
            u64* ac = acc[pr * 2 + pc];
#pragma unroll
            for (int j = 0; j < 8; j++) {
                float2 v = unpk(ac[j]);
                int co = g * 16 + 2 * j;
                float o0 = v.x, o1 = v.y;
                if (bias) { o0 += bias[co]; o1 += bias[co + 1]; }
                if (res)  { o0 += res[base + (size_t)co * cs];
                            o1 += res[base + (size_t)(co + 1) * cs]; }
                if (res2) { o0 += res2[base + (size_t)co * cs];
                            o1 += res2[base + (size_t)(co + 1) * cs]; }
                out[base + (size_t)co * cs]       = o0;
                out[base + (size_t)(co + 1) * cs] = o1;
            }
        }
    }
}

// ---------------- deformable conv, FFMA2, all-tap weights in SMEM ------------
#define DEF_SMEM_FLOATS (9 * 64 * 64)
__global__ void __launch_bounds__(512, 1)
deform_f2_kernel(const float* __restrict__ xpad,    // (B,64,194,194)
                 const float* __restrict__ offset,  // (B,18,192,192)
                 const float* __restrict__ wdc,     // (64,64,3,3)
                 float* __restrict__ out)           // (B,64,192,192)
{
    extern __shared__ __align__(16) float sW[];     // [tap][ci][co]

    const int b   = blockIdx.z;
    const int ty0 = blockIdx.y * 16;
    const int tx0 = blockIdx.x * 32;
    const int tid = threadIdx.x;
    const int py  = tid >> 5, px = tid & 31;
    const int i   = ty0 + py;
    const int j   = tx0 + px;

    for (int idx = tid; idx < 9 * 64 * 64; idx += 512) {
        int tap = idx >> 12;
        int r   = idx & 4095;
        int ci  = r >> 6, co = r & 63;
        sW[idx] = wdc[((size_t)co * 64 + ci) * 9 + tap];
    }
    __syncthreads();

    u64 acc[32];
#pragma unroll
    for (int c = 0; c < 32; c++) acc[c] = 0ull;

#pragma unroll 1
    for (int n = 0; n < NTAP; n++) {
        int dr = n / 3 - 1, dc = n % 3 - 1;
        float offr = offset[(((size_t)b * 18 + n) * HH + i) * WW + j];
        float offc = offset[(((size_t)b * 18 + 9 + n) * HH + i) * WW + j];
        float p_r = (float)(i + 1 + dr) + offr;
        float p_c = (float)(j + 1 + dc) + offc;
        float pr = fminf(fmaxf(p_r, 0.f), 193.f);
        float pc = fminf(fmaxf(p_c, 0.f), 193.f);
        float fr = floorf(p_r), fc = floorf(p_c);
        float qr0 = fminf(fmaxf(fr,       0.f), 193.f);
        float qc0 = fminf(fmaxf(fc,       0.f), 193.f);
        float qr1 = fminf(fmaxf(fr + 1.f, 0.f), 193.f);
        float qc1 = fminf(fmaxf(fc + 1.f, 0.f), 193.f);
        float glt = (1.f + (qr0 - pr)) * (1.f + (qc0 - pc));
        float grb = (1.f - (qr1 - pr)) * (1.f - (qc1 - pc));
        float glb = (1.f + (qr0 - pr)) * (1.f - (qc1 - pc));
        float grt = (1.f - (qr1 - pr)) * (1.f + (qc0 - pc));
        int i00 = (int)qr0 * HP + (int)qc0;
        int i11 = (int)qr1 * HP + (int)qc1;
        int i01 = (int)qr0 * HP + (int)qc1;
        int i10 = (int)qr1 * HP + (int)qc0;

        const float* xb = xpad + (size_t)b * 64 * HP * HP;
        const float* wn = &sW[n * 4096];
#pragma unroll 1
        for (int ci = 0; ci < 64; ci++) {
            const float* xc = xb + (size_t)ci * HP * HP;
            float xo = glt * xc[i00] + grb * xc[i11]
                     + glb * xc[i01] + grt * xc[i10];
            u64 x2 = dup2(xo);
            const ulonglong2* wp = reinterpret_cast<const ulonglong2*>(&wn[ci * 64]);
#pragma unroll
            for (int jj = 0; jj < 16; jj++) {
                ulonglong2 q = wp[jj];
                fma2(acc[2 * jj],     x2, q.x);
                fma2(acc[2 * jj + 1], x2, q.y);
            }
        }
    }

    size_t obase = (size_t)b * 64 * HH * WW + (size_t)i * WW + j;
#pragma unroll
    for (int jj = 0; jj < 32; jj++) {
        float2 v = unpk(acc[jj]);
        out[obase + (size_t)(2 * jj)     * HH * WW] = v.x;
        out[obase + (size_t)(2 * jj + 1) * HH * WW] = v.y;
    }
}

// ---------------- GDN + celu (in place), FFMA2 -------------------------------
__global__ void __launch_bounds__(256, 1)
gdn_celu_kernel(float* __restrict__ x, const float* __restrict__ beta,
                const float* __restrict__ gamma, int HWp)
{
    __shared__ __align__(16) float sG[64 * 64];  // sG[ci*64+co] = gamma[co][ci]
    __shared__ float sB[64];
    const int tid = threadIdx.x;
    for (int idx = tid; idx < 4096; idx += 256) {
        int co = idx & 63, ci = idx >> 6;
        sG[idx] = gamma[co * 64 + ci];
    }
    if (tid < 64) sB[tid] = beta[tid];
    __syncthreads();

    int p = blockIdx.x * 256 + tid;
    if (p >= BB * HWp) return;
    int b = p / HWp, hw = p % HWp;
    float* base = x + (size_t)b * 64 * HWp + hw;

    u64 nrm[32];
#pragma unroll
    for (int jj = 0; jj < 32; jj++) nrm[jj] = pk2(sB[2 * jj], sB[2 * jj + 1]);

    for (int ci = 0; ci < 64; ci++) {
        float v = base[(size_t)ci * HWp];
        u64 sq = dup2(v * v);
        const ulonglong2* gp = reinterpret_cast<const ulonglong2*>(&sG[ci * 64]);
#pragma unroll
        for (int jj = 0; jj < 16; jj++) {
            ulonglong2 q = gp[jj];
            fma2(nrm[2 * jj],     sq, q.x);
            fma2(nrm[2 * jj + 1], sq, q.y);
        }
    }
#pragma unroll
    for (int jj = 0; jj < 32; jj++) {
        float2 nv = unpk(nrm[jj]);
        float v0 = base[(size_t)(2 * jj) * HWp];
        float v1 = base[(size_t)(2 * jj + 1) * HWp];
        float t0 = v0 * rsqrtf(nv.x);
        float t1 = v1 * rsqrtf(nv.y);
        base[(size_t)(2 * jj) * HWp]     = (t0 > 0.f) ? t0 : expm1f(t0);
        base[(size_t)(2 * jj + 1) * HWp] = (t1 > 0.f) ? t1 : expm1f(t1);
    }
}

// ---------------- launcher ---------------------------------------------------
extern "C" void kernel_launch(void* const* d_in, const int* in_sizes, int n_in,
                              void* d_out, int out_size)
{
    const float* f_r     = (const float*)d_in[0];
    const float* m_t     = (const float*)d_in[1];
    const float* w_pconv = (const float*)d_in[2];
    const float* b_pconv = (const float*)d_in[3];
    const float* w_dc    = (const float*)d_in[4];
    const float* w_cat   = (const float*)d_in[5];
    const float* b_cat   = (const float*)d_in[6];
    const float* rb_w1   = (const float*)d_in[7];
    const float* rb_w2   = (const float*)d_in[8];
    const float* rb_beta = (const float*)d_in[9];
    const float* rb_gamma= (const float*)d_in[10];
    float* out = (float*)d_out;

    float *frpad, *offs, *xbuf, *ybuf, *t1;
    cudaGetSymbolAddress((void**)&frpad, g_frpad);
    cudaGetSymbolAddress((void**)&offs,  g_offset);
    cudaGetSymbolAddress((void**)&xbuf,  g_x);
    cudaGetSymbolAddress((void**)&ybuf,  g_y);
    cudaGetSymbolAddress((void**)&t1,    g_t1);

    const int conv_smem = CONV_SMEM_FLOATS * 4;   // 78336 B
    const int def_smem  = DEF_SMEM_FLOATS  * 4;   // 147456 B
    cudaFuncSetAttribute(conv3x3_f2_quad<128, 1, true>,
                         cudaFuncAttributeMaxDynamicSharedMemorySize, conv_smem);
    cudaFuncSetAttribute(conv3x3_f2_pair<64, 0, false>,
                         cudaFuncAttributeMaxDynamicSharedMemorySize, conv_smem);
    cudaFuncSetAttribute(conv3x3_f2_pair<64, 2, false>,
                         cudaFuncAttributeMaxDynamicSharedMemorySize, conv_smem);
    cudaFuncSetAttribute(deform_f2_kernel,
                         cudaFuncAttributeMaxDynamicSharedMemorySize, def_smem);

    // 1. pad f_r
    {
        int total = BB * CC * HP * HP;
        pad_kernel<<<(total + 255) / 256, 256>>>(f_r, frpad);
    }
    // 2. offset = pconv(m_t), pad 1, 64->18
    {
        dim3 grid(12, 12, BB);
        conv3x3_kernel<64, 18, 1, false><<<grid, 256>>>(
            m_t, nullptr, w_pconv, b_pconv, nullptr, offs, HH, WW, HH, WW);
    }
    // 3. x = deform_conv(f_r, offset, w_dc)
    {
        dim3 grid(6, 12, BB);
        deform_f2_kernel<<<grid, 512, def_smem>>>(frpad, offs, w_dc, xbuf);
    }
    // 4. y = conv(cat[x, f_r]), pad 1, 128->64  — QUAD variant (measured best)
    {
        dim3 grid(6, 12, BB);
        conv3x3_f2_quad<128, 1, true><<<grid, 512, conv_smem>>>(
            xbuf, f_r, w_cat, b_cat, nullptr, nullptr, ybuf, HH, WW, HH, WW);
    }
    // 5. resblocks — PAIR variant for CIN=64 (measured best)
    for (int l = 0; l < 3; l++) {
        const float* w1 = rb_w1 + (size_t)l * 64 * 64 * 9;
        const float* w2 = rb_w2 + (size_t)l * 64 * 64 * 9;
        const float* bt = rb_beta + (size_t)l * 64;
        const float* gm = rb_gamma + (size_t)l * 64 * 64;
        // conv1: pad 0, 192 -> 190
        {
            dim3 grid(6, 12, BB);
            conv3x3_f2_pair<64, 0, false><<<grid, 512, conv_smem>>>(
                ybuf, nullptr, w1, nullptr, nullptr, nullptr, t1, HH, WW, 190, 190);
        }
        // gdn + celu in place on t1
        {
            int HWp = 190 * 190;
            int total = BB * HWp;
            gdn_celu_kernel<<<(total + 255) / 256, 256>>>(t1, bt, gm, HWp);
        }
        // conv2: pad 2, 190 -> 192, + residual y.
        // Last layer: also add x (res2) and write straight to harness output.
        {
            dim3 grid(6, 12, BB);
            if (l < 2) {
                conv3x3_f2_pair<64, 2, false><<<grid, 512, conv_smem>>>(
                    t1, nullptr, w2, nullptr, ybuf, nullptr, ybuf, 190, 190, HH, WW);
            } else {
                conv3x3_f2_pair<64, 2, false><<<grid, 512, conv_smem>>>(
                    t1, nullptr, w2, nullptr, ybuf, xbuf, out, 190, 190, HH, WW);
            }
        }
    }
}

// round 17
// speedup vs baseline: 1.1459x; 1.0072x over previous
#include <cuda_runtime.h>
#include <cuda_bf16.h>
#include <math.h>
#include <stdint.h>

// Problem constants
#define BB 2
#define CC 64
#define HH 192
#define WW 192
#define HP 194   // padded
#define NTAP 9

typedef unsigned long long u64;
typedef unsigned int u32;

// ---------------- f32x2 packed helpers --------------------------------------
__device__ __forceinline__ u64 dup2(float x) {
    u64 r; asm("mov.b64 %0, {%1,%1};" : "=l"(r) : "f"(x)); return r;
}
__device__ __forceinline__ u64 pk2(float lo, float hi) {
    u64 r; asm("mov.b64 %0, {%1,%2};" : "=l"(r) : "f"(lo), "f"(hi)); return r;
}
__device__ __forceinline__ void fma2(u64 &d, u64 a, u64 b) {
    asm("fma.rn.f32x2 %0, %1, %2, %0;" : "+l"(d) : "l"(a), "l"(b));
}
__device__ __forceinline__ float2 unpk(u64 v) {
    float2 f; asm("mov.b64 {%0,%1}, %2;" : "=f"(f.x), "=f"(f.y) : "l"(v)); return f;
}

// ---------------- cp.async helpers -------------------------------------------
__device__ __forceinline__ void cpa4(u32 saddr, const void* g, int sz) {
    asm volatile("cp.async.ca.shared.global [%0], [%1], 4, %2;"
                 :: "r"(saddr), "l"(g), "r"(sz));
}
__device__ __forceinline__ void cpa_commit() {
    asm volatile("cp.async.commit_group;");
}
__device__ __forceinline__ void cpa_wait1() {
    asm volatile("cp.async.wait_group 1;");
}

// ---------------- scratch buffers (static device memory; no allocation) -----
__device__ float g_frpad[BB * CC * HP * HP];
__device__ float g_offset[BB * 18 * HH * WW];
__device__ float g_x[BB * CC * HH * WW];
__device__ float g_y[BB * CC * HH * WW];
__device__ float g_t1[BB * CC * 190 * 190];

// ---------------- pad kernel -------------------------------------------------
__global__ void pad_kernel(const float* __restrict__ src, float* __restrict__ dst) {
    int idx = blockIdx.x * blockDim.x + threadIdx.x;
    int total = BB * CC * HP * HP;
    if (idx >= total) return;
    int c2 = idx % HP;
    int r2 = (idx / HP) % HP;
    int bc = idx / (HP * HP);
    float v = 0.f;
    if (r2 >= 1 && r2 <= HH && c2 >= 1 && c2 <= WW)
        v = src[(size_t)bc * HH * WW + (r2 - 1) * WW + (c2 - 1)];
    dst[idx] = v;
}

// ---------------- generic 3x3 conv (kept for pconv, COUT=18) -----------------
template<int CIN, int COUT, int PADV, bool HAS_IN2>
__global__ void __launch_bounds__(256, 1)
conv3x3_kernel(const float* __restrict__ inA, const float* __restrict__ inB,
               const float* __restrict__ w, const float* __restrict__ bias,
               const float* __restrict__ res, float* __restrict__ out,
               int Hin, int Win, int Hout, int Wout)
{
    constexpr int CH = 8;
    constexpr int COUT_P = (COUT + 3) & ~3;
    __shared__ __align__(16) float sIn[CH][18][18];
    __shared__ __align__(16) float sW[CH * 9 * COUT_P];

    const int b   = blockIdx.z;
    const int ty0 = blockIdx.y * 16;
    const int tx0 = blockIdx.x * 16;
    const int tid = threadIdx.x;
    const int py = tid >> 4, px = tid & 15;
    const int oy = ty0 + py, ox = tx0 + px;

    float acc[COUT_P];
#pragma unroll
    for (int i = 0; i < COUT_P; i++) acc[i] = 0.f;

    const int cstride = HAS_IN2 ? 64 : CIN;

    for (int c0 = 0; c0 < CIN; c0 += CH) {
        for (int idx = tid; idx < CH * 18 * 18; idx += 256) {
            int c   = idx / (18 * 18);
            int rem = idx % (18 * 18);
            int r = rem / 18, cc = rem % 18;
            int iy = ty0 - PADV + r;
            int ix = tx0 - PADV + cc;
            float v = 0.f;
            if (iy >= 0 && iy < Hin && ix >= 0 && ix < Win) {
                int ci = c0 + c;
                const float* src = inA;
                int cl = ci;
                if (HAS_IN2 && ci >= 64) { src = inB; cl = ci - 64; }
                v = src[(((size_t)b * cstride + cl) * Hin + iy) * Win + ix];
            }
            sIn[c][r][cc] = v;
        }
        for (int idx = tid; idx < CH * 9 * COUT_P; idx += 256) {
            int co = idx % COUT_P;
            int ck = idx / COUT_P;
            int ci_l = ck / 9, k = ck % 9;
            float v = 0.f;
            if (co < COUT) v = w[((size_t)co * CIN + (c0 + ci_l)) * 9 + k];
            sW[idx] = v;
        }
        __syncthreads();

        for (int ci = 0; ci < CH; ci++) {
#pragma unroll
            for (int ky = 0; ky < 3; ky++) {
#pragma unroll
                for (int kx = 0; kx < 3; kx++) {
                    float xv = sIn[ci][py + ky][px + kx];
                    const float4* wp = reinterpret_cast<const float4*>(
                        &sW[(ci * 9 + ky * 3 + kx) * COUT_P]);
#pragma unroll
                    for (int j = 0; j < COUT_P / 4; j++) {
                        float4 w4 = wp[j];
                        acc[4 * j + 0] = fmaf(w4.x, xv, acc[4 * j + 0]);
                        acc[4 * j + 1] = fmaf(w4.y, xv, acc[4 * j + 1]);
                        acc[4 * j + 2] = fmaf(w4.z, xv, acc[4 * j + 2]);
                        acc[4 * j + 3] = fmaf(w4.w, xv, acc[4 * j + 3]);
                    }
                }
            }
        }
        __syncthreads();
    }

    if (oy < Hout && ox < Wout) {
        size_t obase = (size_t)b * COUT * Hout * Wout + (size_t)oy * Wout + ox;
        size_t cs = (size_t)Hout * Wout;
#pragma unroll
        for (int co = 0; co < COUT; co++) {
            float v = acc[co];
            if (bias) v += bias[co];
            if (res)  v += res[obase + co * cs];
            out[obase + co * cs] = v;
        }
    }
}

// SMEM layout (512 threads, 16x32 tile, chunk = CH input channels):
//   IN(buf) = buf*CH*648 : [CH][18][36] (34 cols used)
//   W(buf)  = 2*CH*648 + buf*CH*576 : [CH][9][64]
#define CONV_CH 16
#define CONV_SMEM_FLOATS (2*CONV_CH*648 + 2*CONV_CH*576)

// ---------------- staging geometry shared by both variants -------------------
// (division-free cp.async staging; hoisted per-thread positions)
#define CONV_STAGE_DECLS                                                      \
    const int HinWin = Hin * Win;                                             \
    const u32 smem_base = (u32)__cvta_generic_to_shared(sm);                  \
    const int p0_ = tid;                                                      \
    const int r0_ = p0_ / 34, q0_ = p0_ % 34;                                 \
    const int iy0_ = ty0 - PADV + r0_, ix0_ = tx0 - PADV + q0_;               \
    const bool ok0_ = (iy0_ >= 0 && iy0_ < Hin && ix0_ >= 0 && ix0_ < Win);   \
    const int go0_ = iy0_ * Win + ix0_;                                       \
    const u32 so0_ = (u32)((r0_ * 36 + q0_) * 4);                             \
    const int p1_ = tid + 512;                                                \
    const bool has1_ = (p1_ < 612);                                           \
    const int r1_ = p1_ / 34, q1_ = p1_ % 34;                                 \
    const int iy1_ = ty0 - PADV + r1_, ix1_ = tx0 - PADV + q1_;               \
    const bool ok1_ = has1_ && (iy1_ >= 0 && iy1_ < Hin && ix1_ >= 0 && ix1_ < Win); \
    const int go1_ = iy1_ * Win + ix1_;                                       \
    const u32 so1_ = (u32)((r1_ * 36 + q1_) * 4);                             \
    const int wco_ = tid & 63;                                                \
    const int wp0_ = tid >> 6;                                                \
    const size_t wbase0_ = (size_t)wco_ * CIN * 9 + wp0_;                     \
    auto stage = [&](int buf, int cc0_) {                                     \
        const float* srcb;                                                    \
        if (HAS_IN2 && cc0_ >= 64)                                            \
            srcb = inB + ((size_t)b * 64 + (cc0_ - 64)) * HinWin;             \
        else                                                                  \
            srcb = inA + ((size_t)b * cstride + cc0_) * HinWin;               \
        const u32 sbase = smem_base + (u32)(buf * CH * 648 * 4);              \
        {                                                                     \
            const float* gp = ok0_ ? (srcb + go0_) : srcb;                    \
            const int step = ok0_ ? HinWin : 0;                               \
            const int sz = ok0_ ? 4 : 0;                                      \
            u32 sa = sbase + so0_;                                            \
            _Pragma("unroll")                                                 \
            for (int c = 0; c < CH; c++) { cpa4(sa, gp, sz); gp += step; sa += 648 * 4; } \
        }                                                                     \
        if (has1_) {                                                          \
            const float* gp = ok1_ ? (srcb + go1_) : srcb;                    \
            const int step = ok1_ ? HinWin : 0;                               \
            const int sz = ok1_ ? 4 : 0;                                      \
            u32 sa = sbase + so1_;                                            \
            _Pragma("unroll")                                                 \
            for (int c = 0; c < CH; c++) { cpa4(sa, gp, sz); gp += step; sa += 648 * 4; } \
        }                                                                     \
        {                                                                     \
            const float* gp = w + wbase0_ + (size_t)cc0_ * 9;                 \
            u32 sa = smem_base + (u32)((2 * CH * 648 + buf * CH * 576 + wp0_ * 64 + wco_) * 4); \
            _Pragma("unroll")                                                 \
            for (int m = 0; m < CH * 9 / 8; m++) { cpa4(sa, gp, 4); gp += 8; sa += 2048; } \
        }                                                                     \
    };

// ---------------- PAIR variant: 1x2 px x 32 couts — best for CIN=64 ----------
template<int CIN, int PADV, bool HAS_IN2>
__global__ void __launch_bounds__(512, 1)
conv3x3_f2_pair(const float* __restrict__ inA, const float* __restrict__ inB,
                const float* __restrict__ w, const float* __restrict__ bias,
                const float* __restrict__ res, const float* __restrict__ res2,
                float* __restrict__ out,
                int Hin, int Win, int Hout, int Wout)
{
    constexpr int CH = CONV_CH;
    constexpr int NC = CIN / CH;
    extern __shared__ __align__(16) float sm[];

    const int b   = blockIdx.z;
    const int ty0 = blockIdx.y * 16;
    const int tx0 = blockIdx.x * 32;
    const int tid = threadIdx.x;
    const int g   = tid >> 8;          // cout half
    const int t   = tid & 255;
    const int qy  = t >> 4;            // 0..15 output row
    const int qx  = t & 15;            // 0..15 output col pair

    const int cstride = HAS_IN2 ? 64 : CIN;
    CONV_STAGE_DECLS

    u64 acc[2][16];
#pragma unroll
    for (int p = 0; p < 2; p++)
#pragma unroll
        for (int j = 0; j < 16; j++) acc[p][j] = 0ull;

    stage(0, 0);
    cpa_commit();

    for (int c = 0; c < NC; c++) {
        int buf = c & 1;
        if (c + 1 < NC) stage(buf ^ 1, (c + 1) * CH);
        cpa_commit();
        cpa_wait1();
        __syncthreads();

        const float* sIn = sm + buf * CH * 648;                  // [CH][18][36]
        const float* sW  = sm + 2 * CH * 648 + buf * CH * 576;   // [CH][9][64]

#pragma unroll 1
        for (int ci = 0; ci < CH; ci++) {
            u64 d[3][4];
#pragma unroll
            for (int r = 0; r < 3; r++) {
                const float2* ip = reinterpret_cast<const float2*>(
                    &sIn[(ci * 18 + qy + r) * 36 + 2 * qx]);
                float2 a = ip[0], bb = ip[1];
                d[r][0] = dup2(a.x); d[r][1] = dup2(a.y);
                d[r][2] = dup2(bb.x); d[r][3] = dup2(bb.y);
            }
#pragma unroll
            for (int ky = 0; ky < 3; ky++) {
#pragma unroll
                for (int kx = 0; kx < 3; kx++) {
                    u64 xv0 = d[ky][kx];
                    u64 xv1 = d[ky][kx + 1];
                    const ulonglong2* wp = reinterpret_cast<const ulonglong2*>(
                        &sW[(ci * 9 + ky * 3 + kx) * 64 + g * 32]);
#pragma unroll
                    for (int j = 0; j < 8; j++) {
                        ulonglong2 q = wp[j];
                        fma2(acc[0][2 * j],     xv0, q.x);
                        fma2(acc[0][2 * j + 1], xv0, q.y);
                        fma2(acc[1][2 * j],     xv1, q.x);
                        fma2(acc[1][2 * j + 1], xv1, q.y);
                    }
                }
            }
        }
        __syncthreads();
    }

    size_t cs = (size_t)Hout * Wout;
    int oy = ty0 + qy;
#pragma unroll
    for (int pc = 0; pc < 2; pc++) {
        int ox = tx0 + 2 * qx + pc;
        if (oy < Hout && ox < Wout) {
            size_t base = (size_t)b * 64 * cs + (size_t)oy * Wout + ox;
            u64* ac = acc[pc];
#pragma unroll
            for (int j = 0; j < 16; j++) {
                float2 v = unpk(ac[j]);
                int co = g * 32 + 2 * j;
                float o0 = v.x, o1 = v.y;
                if (bias) { o0 += bias[co]; o1 += bias[co + 1]; }
                if (res)  { o0 += res[base + (size_t)co * cs];
                            o1 += res[base + (size_t)(co + 1) * cs]; }
                if (res2) { o0 += res2[base + (size_t)co * cs];
                            o1 += res2[base + (size_t)(co + 1) * cs]; }
                out[base + (size_t)co * cs]       = o0;
                out[base + (size_t)(co + 1) * cs] = o1;
            }
        }
    }
}

// ---------------- QUAD variant: 2x2 px x 16 couts — best for CIN=128 ---------
template<int CIN, int PADV, bool HAS_IN2>
__global__ void __launch_bounds__(512, 1)
conv3x3_f2_quad(const float* __restrict__ inA, const float* __restrict__ inB,
                const float* __restrict__ w, const float* __restrict__ bias,
                const float* __restrict__ res, const float* __restrict__ res2,
                float* __restrict__ out,
                int Hin, int Win, int Hout, int Wout)
{
    constexpr int CH = CONV_CH;
    constexpr int NC = CIN / CH;
    extern __shared__ __align__(16) float sm[];

    const int b   = blockIdx.z;
    const int ty0 = blockIdx.y * 16;
    const int tx0 = blockIdx.x * 32;
    const int tid = threadIdx.x;
    const int g   = tid >> 7;          // cout group 0..3 (16 couts)
    const int t   = tid & 127;
    const int ty  = t >> 4;            // 0..7  output row pair
    const int qx  = t & 15;            // 0..15 output col pair

    const int cstride = HAS_IN2 ? 64 : CIN;
    CONV_STAGE_DECLS

    u64 acc[4][8];
#pragma unroll
    for (int p = 0; p < 4; p++)
#pragma unroll
        for (int j = 0; j < 8; j++) acc[p][j] = 0ull;

    stage(0, 0);
    cpa_commit();

    for (int c = 0; c < NC; c++) {
        int buf = c & 1;
        if (c + 1 < NC) stage(buf ^ 1, (c + 1) * CH);
        cpa_commit();
        cpa_wait1();
        __syncthreads();

        const float* sIn = sm + buf * CH * 648;                  // [CH][18][36]
        const float* sW  = sm + 2 * CH * 648 + buf * CH * 576;   // [CH][9][64]

#pragma unroll 1
        for (int ci = 0; ci < CH; ci++) {
#pragma unroll
            for (int ky = 0; ky < 3; ky++) {
                u64 d[2][4];
#pragma unroll
                for (int r = 0; r < 2; r++) {
                    const float2* ip = reinterpret_cast<const float2*>(
                        &sIn[(ci * 18 + 2 * ty + ky + r) * 36 + 2 * qx]);
                    float2 a = ip[0], bb = ip[1];
                    d[r][0] = dup2(a.x); d[r][1] = dup2(a.y);
                    d[r][2] = dup2(bb.x); d[r][3] = dup2(bb.y);
                }
#pragma unroll
                for (int kx = 0; kx < 3; kx++) {
                    const ulonglong2* wp = reinterpret_cast<const ulonglong2*>(
                        &sW[(ci * 9 + ky * 3 + kx) * 64 + g * 16]);
                    ulonglong2 w01 = wp[0];
                    ulonglong2 w23 = wp[1];
#pragma unroll
                    for (int pr = 0; pr < 2; pr++) {
#pragma unroll
                        for (int pc = 0; pc < 2; pc++) {
                            u64 xv = d[pr][pc + kx];
                            u64* a = acc[pr * 2 + pc];
                            fma2(a[0], xv, w01.x);
                            fma2(a[1], xv, w01.y);
                            fma2(a[2], xv, w23.x);
                            fma2(a[3], xv, w23.y);
                        }
                    }
                    ulonglong2 w45 = wp[2];
                    ulonglong2 w67 = wp[3];
#pragma unroll
                    for (int pr = 0; pr < 2; pr++) {
#pragma unroll
                        for (int pc = 0; pc < 2; pc++) {
                            u64 xv = d[pr][pc + kx];
                            u64* a = acc[pr * 2 + pc];
                            fma2(a[4], xv, w45.x);
                            fma2(a[5], xv, w45.y);
                            fma2(a[6], xv, w67.x);
                            fma2(a[7], xv, w67.y);
                        }
                    }
                }
            }
        }
        __syncthreads();
    }

    size_t cs = (size_t)Hout * Wout;
#pragma unroll
    for (int pr = 0; pr < 2; pr++) {
        int oy = ty0 + 2 * ty + pr;
        if (oy >= Hout) continue;
#pragma unroll
        for (int pc = 0; pc < 2; pc++) {
            int ox = tx0 + 2 * qx + pc;
            if (ox >= Wout) continue;
            size_t base = (size_t)b * 64 * cs + (size_t)oy * Wout + ox;
            u64* ac = acc[pr * 2 + pc];
#pragma unroll
            for (int j = 0; j < 8; j++) {
                float2 v = unpk(ac[j]);
                int co = g * 16 + 2 * j;
                float o0 = v.x, o1 = v.y;
                if (bias) { o0 += bias[co]; o1 += bias[co + 1]; }
                if (res)  { o0 += res[base + (size_t)co * cs];
                            o1 += res[base + (size_t)(co + 1) * cs]; }
                if (res2) { o0 += res2[base + (size_t)co * cs];
                            o1 += res2[base + (size_t)(co + 1) * cs]; }
                out[base + (size_t)co * cs]       = o0;
                out[base + (size_t)(co + 1) * cs] = o1;
            }
        }
    }
}

// ---------------- deformable conv, FFMA2, all-tap weights in SMEM ------------
#define DEF_SMEM_FLOATS (9 * 64 * 64)
__global__ void __launch_bounds__(512, 1)
deform_f2_kernel(const float* __restrict__ xpad,    // (B,64,194,194)
                 const float* __restrict__ offset,  // (B,18,192,192)
                 const float* __restrict__ wdc,     // (64,64,3,3)
                 float* __restrict__ out)           // (B,64,192,192)
{
    extern __shared__ __align__(16) float sW[];     // [tap][ci][co]

    const int b   = blockIdx.z;
    const int ty0 = blockIdx.y * 16;
    const int tx0 = blockIdx.x * 32;
    const int tid = threadIdx.x;
    const int py  = tid >> 5, px = tid & 31;
    const int i   = ty0 + py;
    const int j   = tx0 + px;

    for (int idx = tid; idx < 9 * 64 * 64; idx += 512) {
        int tap = idx >> 12;
        int r   = idx & 4095;
        int ci  = r >> 6, co = r & 63;
        sW[idx] = wdc[((size_t)co * 64 + ci) * 9 + tap];
    }
    __syncthreads();

    u64 acc[32];
#pragma unroll
    for (int c = 0; c < 32; c++) acc[c] = 0ull;

#pragma unroll 1
    for (int n = 0; n < NTAP; n++) {
        int dr = n / 3 - 1, dc = n % 3 - 1;
        float offr = offset[(((size_t)b * 18 + n) * HH + i) * WW + j];
        float offc = offset[(((size_t)b * 18 + 9 + n) * HH + i) * WW + j];
        float p_r = (float)(i + 1 + dr) + offr;
        float p_c = (float)(j + 1 + dc) + offc;
        float pr = fminf(fmaxf(p_r, 0.f), 193.f);
        float pc = fminf(fmaxf(p_c, 0.f), 193.f);
        float fr = floorf(p_r), fc = floorf(p_c);
        float qr0 = fminf(fmaxf(fr,       0.f), 193.f);
        float qc0 = fminf(fmaxf(fc,       0.f), 193.f);
        float qr1 = fminf(fmaxf(fr + 1.f, 0.f), 193.f);
        float qc1 = fminf(fmaxf(fc + 1.f, 0.f), 193.f);
        float glt = (1.f + (qr0 - pr)) * (1.f + (qc0 - pc));
        float grb = (1.f - (qr1 - pr)) * (1.f - (qc1 - pc));
        float glb = (1.f + (qr0 - pr)) * (1.f - (qc1 - pc));
        float grt = (1.f - (qr1 - pr)) * (1.f + (qc0 - pc));
        int i00 = (int)qr0 * HP + (int)qc0;
        int i11 = (int)qr1 * HP + (int)qc1;
        int i01 = (int)qr0 * HP + (int)qc1;
        int i10 = (int)qr1 * HP + (int)qc0;

        const float* xb = xpad + (size_t)b * 64 * HP * HP;
        const float* wn = &sW[n * 4096];
#pragma unroll 1
        for (int ci = 0; ci < 64; ci++) {
            const float* xc = xb + (size_t)ci * HP * HP;
            float xo = glt * xc[i00] + grb * xc[i11]
                     + glb * xc[i01] + grt * xc[i10];
            u64 x2 = dup2(xo);
            const ulonglong2* wp = reinterpret_cast<const ulonglong2*>(&wn[ci * 64]);
#pragma unroll
            for (int jj = 0; jj < 16; jj++) {
                ulonglong2 q = wp[jj];
                fma2(acc[2 * jj],     x2, q.x);
                fma2(acc[2 * jj + 1], x2, q.y);
            }
        }
    }

    size_t obase = (size_t)b * 64 * HH * WW + (size_t)i * WW + j;
#pragma unroll
    for (int jj = 0; jj < 32; jj++) {
        float2 v = unpk(acc[jj]);
        out[obase + (size_t)(2 * jj)     * HH * WW] = v.x;
        out[obase + (size_t)(2 * jj + 1) * HH * WW] = v.y;
    }
}

// ---------------- GDN + celu (in place), FFMA2 -------------------------------
__global__ void __launch_bounds__(256, 1)
gdn_celu_kernel(float* __restrict__ x, const float* __restrict__ beta,
                const float* __restrict__ gamma, int HWp)
{
    __shared__ __align__(16) float sG[64 * 64];  // sG[ci*64+co] = gamma[co][ci]
    __shared__ float sB[64];
    const int tid = threadIdx.x;
    for (int idx = tid; idx < 4096; idx += 256) {
        int co = idx & 63, ci = idx >> 6;
        sG[idx] = gamma[co * 64 + ci];
    }
    if (tid < 64) sB[tid] = beta[tid];
    __syncthreads();

    int p = blockIdx.x * 256 + tid;
    if (p >= BB * HWp) return;
    int b = p / HWp, hw = p % HWp;
    float* base = x + (size_t)b * 64 * HWp + hw;

    u64 nrm[32];
#pragma unroll
    for (int jj = 0; jj < 32; jj++) nrm[jj] = pk2(sB[2 * jj], sB[2 * jj + 1]);

    for (int ci = 0; ci < 64; ci++) {
        float v = base[(size_t)ci * HWp];
        u64 sq = dup2(v * v);
        const ulonglong2* gp = reinterpret_cast<const ulonglong2*>(&sG[ci * 64]);
#pragma unroll
        for (int jj = 0; jj < 16; jj++) {
            ulonglong2 q = gp[jj];
            fma2(nrm[2 * jj],     sq, q.x);
            fma2(nrm[2 * jj + 1], sq, q.y);
        }
    }
#pragma unroll
    for (int jj = 0; jj < 32; jj++) {
        float2 nv = unpk(nrm[jj]);
        float v0 = base[(size_t)(2 * jj) * HWp];
        float v1 = base[(size_t)(2 * jj + 1) * HWp];
        float t0 = v0 * rsqrtf(nv.x);
        float t1 = v1 * rsqrtf(nv.y);
        base[(size_t)(2 * jj) * HWp]     = (t0 > 0.f) ? t0 : expm1f(t0);
        base[(size_t)(2 * jj + 1) * HWp] = (t1 > 0.f) ? t1 : expm1f(t1);
    }
}

// ---------------- launcher ---------------------------------------------------
extern "C" void kernel_launch(void* const* d_in, const int* in_sizes, int n_in,
                              void* d_out, int out_size)
{
    const float* f_r     = (const float*)d_in[0];
    const float* m_t     = (const float*)d_in[1];
    const float* w_pconv = (const float*)d_in[2];
    const float* b_pconv = (const float*)d_in[3];
    const float* w_dc    = (const float*)d_in[4];
    const float* w_cat   = (const float*)d_in[5];
    const float* b_cat   = (const float*)d_in[6];
    const float* rb_w1   = (const float*)d_in[7];
    const float* rb_w2   = (const float*)d_in[8];
    const float* rb_beta = (const float*)d_in[9];
    const float* rb_gamma= (const float*)d_in[10];
    float* out = (float*)d_out;

    float *frpad, *offs, *xbuf, *ybuf, *t1;
    cudaGetSymbolAddress((void**)&frpad, g_frpad);
    cudaGetSymbolAddress((void**)&offs,  g_offset);
    cudaGetSymbolAddress((void**)&xbuf,  g_x);
    cudaGetSymbolAddress((void**)&ybuf,  g_y);
    cudaGetSymbolAddress((void**)&t1,    g_t1);

    const int conv_smem = CONV_SMEM_FLOATS * 4;   // 156672 B
    const int def_smem  = DEF_SMEM_FLOATS  * 4;   // 147456 B
    cudaFuncSetAttribute(conv3x3_f2_quad<128, 1, true>,
                         cudaFuncAttributeMaxDynamicSharedMemorySize, conv_smem);
    cudaFuncSetAttribute(conv3x3_f2_pair<64, 0, false>,
                         cudaFuncAttributeMaxDynamicSharedMemorySize, conv_smem);
    cudaFuncSetAttribute(conv3x3_f2_pair<64, 2, false>,
                         cudaFuncAttributeMaxDynamicSharedMemorySize, conv_smem);
    cudaFuncSetAttribute(deform_f2_kernel,
                         cudaFuncAttributeMaxDynamicSharedMemorySize, def_smem);

    // 1. pad f_r
    {
        int total = BB * CC * HP * HP;
        pad_kernel<<<(total + 255) / 256, 256>>>(f_r, frpad);
    }
    // 2. offset = pconv(m_t), pad 1, 64->18
    {
        dim3 grid(12, 12, BB);
        conv3x3_kernel<64, 18, 1, false><<<grid, 256>>>(
            m_t, nullptr, w_pconv, b_pconv, nullptr, offs, HH, WW, HH, WW);
    }
    // 3. x = deform_conv(f_r, offset, w_dc)
    {
        dim3 grid(6, 12, BB);
        deform_f2_kernel<<<grid, 512, def_smem>>>(frpad, offs, w_dc, xbuf);
    }
    // 4. y = conv(cat[x, f_r]), pad 1, 128->64  — QUAD variant
    {
        dim3 grid(6, 12, BB);
        conv3x3_f2_quad<128, 1, true><<<grid, 512, conv_smem>>>(
            xbuf, f_r, w_cat, b_cat, nullptr, nullptr, ybuf, HH, WW, HH, WW);
    }
    // 5. resblocks — PAIR variant for CIN=64
    for (int l = 0; l < 3; l++) {
        const float* w1 = rb_w1 + (size_t)l * 64 * 64 * 9;
        const float* w2 = rb_w2 + (size_t)l * 64 * 64 * 9;
        const float* bt = rb_beta + (size_t)l * 64;
        const float* gm = rb_gamma + (size_t)l * 64 * 64;
        // conv1: pad 0, 192 -> 190
        {
            dim3 grid(6, 12, BB);
            conv3x3_f2_pair<64, 0, false><<<grid, 512, conv_smem>>>(
                ybuf, nullptr, w1, nullptr, nullptr, nullptr, t1, HH, WW, 190, 190);
        }
        // gdn + celu in place on t1
        {
            int HWp = 190 * 190;
            int total = BB * HWp;
            gdn_celu_kernel<<<(total + 255) / 256, 256>>>(t1, bt, gm, HWp);
        }
        // conv2: pad 2, 190 -> 192, + residual y.
        // Last layer: also add x (res2) and write straight to harness output.
        {
            dim3 grid(6, 12, BB);
            if (l < 2) {
                conv3x3_f2_pair<64, 2, false><<<grid, 512, conv_smem>>>(
                    t1, nullptr, w2, nullptr, ybuf, nullptr, ybuf, 190, 190, HH, WW);
            } else {
                conv3x3_f2_pair<64, 2, false><<<grid, 512, conv_smem>>>(
                    t1, nullptr, w2, nullptr, ybuf, xbuf, out, 190, 190, HH, WW);
            }
        }
    }
}